// round 5
// baseline (speedup 1.0000x reference)
#include <cuda_runtime.h>
#include <float.h>

// Problem constants
#define HH 512
#define WW 512
#define MBS 8          // macroblock size
#define PR 8           // search range
#define NBR 64
#define NBC 64
#define NPAIR 14       // frame pairs actually used (motion[:-1])
#define NBATCH 4
#define CROPX 17
#define OUTD 478       // 512 - 2*17
#define LARGEC 65537.0f
#define MAX_STEPS 16
#define SW 84          // padded smem window stride (cols)

// Motion vectors scratch: (dy, dx) per block. Static device global (no allocs).
__device__ int2 g_motion[NBATCH * NPAIR * NBR * NBC];

// LDSP points as (dx, dy) matching reference ordering; cost uses (y+dy, x+dx).
__constant__ int c_ldsp_dx[9] = { 0, -1, 1, -2, 0, 2, -1, 1, 0 };
__constant__ int c_ldsp_dy[9] = { -2, -1, -1, 0, 0, 0, 1, 1, 2 };
__constant__ int c_sdsp_dx[5] = { 0, -1, 0, 1, 0 };
__constant__ int c_sdsp_dy[5] = { -1, 0, 0, 0, 1 };

// One CTA: 8 macroblocks of one block-row segment. 128 threads = 8 groups of 16.
// Per group: lanes 0-8 evaluate the 9 LDSP candidates; lanes 9-13 speculatively
// evaluate the 5 SDSP candidates at the SAME center. When the loop exits with
// pt==4 the speculative SDSP costs equal the reference's final SDSP round.
// SAD accumulation replicates XLA GPU's row-reduction association:
//   pacc[t] = |d|[t] + |d|[t+32], then tree offsets 16,8,4,2,1 (bit-exact argmin).
// Block pixels live in registers (reused across all rounds); only window reads
// hit the smem crossbar, which is this kernel's binding resource.
__global__ __launch_bounds__(128, 4) void motion_kernel(const float* __restrict__ x) {
    __shared__ float swin[24 * SW];   // reference window rows [i-8, i+16), cols [j0-8, j0+72)
    __shared__ float sblk[8 * 64];    // current-frame blocks for this tile

    const int jt  = blockIdx.x;              // col tile 0..7
    const int bi  = blockIdx.y;              // block row 0..63
    const int bp_ = blockIdx.z;              // b*NPAIR + p, 0..55
    const int b   = bp_ / NPAIR;
    const int p   = bp_ % NPAIR;

    const float* imgI = x + (size_t)(b * 16 + p) * HH * WW;       // reference (t-1)
    const float* imgP = imgI + (size_t)HH * WW;                   // current  (t)

    const int i  = bi * MBS;
    const int j0 = jt * 64;
    const int tid = threadIdx.x;

    // Cooperative loads (clamped; out-of-range rows/cols only back invalid candidates)
    for (int t = tid; t < 24 * 80; t += 128) {
        int r = t / 80, c = t - (t / 80) * 80;
        int gr = i - 8 + r;  gr = gr < 0 ? 0 : (gr > HH - 1 ? HH - 1 : gr);
        int gc = j0 - 8 + c; gc = gc < 0 ? 0 : (gc > WW - 1 ? WW - 1 : gc);
        swin[r * SW + c] = imgI[gr * WW + gc];
    }
    for (int t = tid; t < 8 * 64; t += 128) {
        int r = t >> 6, c = t & 63;
        sblk[t] = imgP[(i + r) * WW + (j0 + c)];
    }
    __syncthreads();

    const int g  = tid >> 4;       // group (macroblock) 0..7
    const int lg = tid & 15;       // lane in group
    const unsigned gmask = 0xFFFFu << (tid & 16);
    const int j = j0 + g * 8;

    // Block in registers: reused every round, zero crossbar cost thereafter.
    float bp[64];
#pragma unroll
    for (int r = 0; r < 8; r++)
#pragma unroll
        for (int c = 0; c < 8; c++)
            bp[r * 8 + c] = sblk[r * 64 + g * 8 + c];

    // SAD mean, XLA association, first tree level fused into the element loop:
    //   s[u] = (d[u] + d[u+32]) + (d[u+16] + d[u+48]),  u = 0..15
    // then tree offsets 8,4,2,1. 64 window LDS.32, 16 live partials.
    auto evalc = [&](int cy, int cx) -> float {
        const float* wp = &swin[(cy - i + 8) * SW + (cx - j0 + 8)];
        float s[16];
#pragma unroll
        for (int u = 0; u < 16; u++) {
            int r0 = u >> 3, c0_ = u & 7;   // u -> rows 0-1; +16 -> 2-3; +32 -> 4-5; +48 -> 6-7
            float d0 = fabsf(bp[u]      - wp[(r0    ) * SW + c0_]);
            float d2 = fabsf(bp[u + 32] - wp[(r0 + 4) * SW + c0_]);
            float p0 = d0 + d2;                         // pacc[u]
            float d1 = fabsf(bp[u + 16] - wp[(r0 + 2) * SW + c0_]);
            float d3 = fabsf(bp[u + 48] - wp[(r0 + 6) * SW + c0_]);
            float p1 = d1 + d3;                         // pacc[u+16]
            s[u] = p0 + p1;                             // tree level off=16
        }
#pragma unroll
        for (int off = 8; off >= 1; off >>= 1)
#pragma unroll
            for (int t = 0; t < 8; t++)
                if (t < off) s[t] = s[t] + s[t + off];
        return s[0] * 0.015625f;
    };

    auto costat = [&](int cy, int cx) -> float {
        bool valid = (cy >= 0) && (cy + MBS <= HH) && (cx >= 0) && (cx + MBS <= WW)
                   && (cy - i <= PR) && (i - cy <= PR) && (cx - j <= PR) && (j - cx <= PR);
        float cst = LARGEC;
        if (valid) cst = evalc(cy, cx);
        return cst;
    };

    // Lane role: 0-8 LDSP, 9-13 SDSP(lg-9), 14-15 dup SDSP center (unused).
    const bool isldsp = (lg < 9);
    const int  sdi    = (lg >= 9 && lg < 14) ? (lg - 9) : 2;
    const int  mdy    = isldsp ? c_ldsp_dy[lg] : c_sdsp_dy[sdi];
    const int  mdx    = isldsp ? c_ldsp_dx[lg] : c_sdsp_dx[sdi];

    int y = i, xx = j;
    float my_sdsp = FLT_MAX;
    bool have_sdsp = false;

    for (int k = 0; k < MAX_STEPS; k++) {
        float cost = costat(y + mdy, xx + mdx);
        if (lg >= 9) my_sdsp = cost;

        if (k == 0) {
            // Reference's standalone c0 check == this iteration's lane 4 cost.
            float ctr = __shfl_sync(gmask, cost, 4, 16);
            if (ctr == 0.0f) { have_sdsp = true; break; }
        }

        // LDSP argmin: lexicographic (cost, idx) == jnp.argmin first-index
        float cc = isldsp ? cost : FLT_MAX;
        int  idx = isldsp ? lg : 15;
#pragma unroll
        for (int off = 8; off >= 1; off >>= 1) {
            float oc = __shfl_xor_sync(gmask, cc, off, 16);
            int   oi = __shfl_xor_sync(gmask, idx, off, 16);
            if (oc < cc || (oc == cc && oi < idx)) { cc = oc; idx = oi; }
        }
        if (idx == 4) { have_sdsp = true; break; }   // center: speculative SDSP valid
        y  += c_ldsp_dy[idx];
        xx += c_ldsp_dx[idx];
    }

    // SDSP refinement: use speculative costs, or (rare: MAX_STEPS exit) recompute.
    {
        float sv = FLT_MAX;
        int   si = 15;
        if (have_sdsp) {
            if (lg >= 9 && lg < 14) { sv = my_sdsp; si = lg - 9; }
        } else {
            if (lg < 5) { sv = costat(y + c_sdsp_dy[lg], xx + c_sdsp_dx[lg]); si = lg; }
        }
#pragma unroll
        for (int off = 8; off >= 1; off >>= 1) {
            float oc = __shfl_xor_sync(gmask, sv, off, 16);
            int   oi = __shfl_xor_sync(gmask, si, off, 16);
            if (oc < sv || (oc == sv && oi < si)) { sv = oc; si = oi; }
        }
        y  += c_sdsp_dy[si];
        xx += c_sdsp_dx[si];
    }

    if (lg == 0) {
        g_motion[(bp_ * NBR + bi) * NBC + (jt * 8 + g)] = make_int2(y - i, xx - j);
    }
}

// Output: first half = target (crop of frame f+2), second half = pred
// (motion-compensated warp of frame f+1 through g_motion, cropped).
// 2 rows per thread -> 4 independent loads in flight (L2-latency bound).
__global__ void out_kernel(const float* __restrict__ x, float* __restrict__ out) {
    int c = blockIdx.x * blockDim.x + threadIdx.x;
    if (c >= OUTD) return;
    int r0 = blockIdx.y * 2;          // rows r0, r0+1 (OUTD=478 even)
    int z  = blockIdx.z;              // b*NPAIR + f
    int b = z / NPAIR;
    int f = z - b * NPAIR;

    const float* base = x + (size_t)b * 16 * HH * WW;
    const float* tgt  = base + (size_t)(f + 2) * HH * WW;
    const float* ref  = base + (size_t)(f + 1) * HH * WW;
    const size_t TOT = (size_t)NBATCH * NPAIR * OUTD * OUTD;

    int C = CROPX + c;
    int R0 = CROPX + r0, R1 = R0 + 1;
    size_t o0 = ((size_t)z * OUTD + r0) * OUTD + c;
    size_t o1 = o0 + OUTD;

    // Independent loads first (MLP), then stores.
    float t0 = tgt[(size_t)R0 * WW + C];
    float t1 = tgt[(size_t)R1 * WW + C];
    int2 m0 = g_motion[((b * NPAIR + f) * NBR + (R0 >> 3)) * NBC + (C >> 3)];
    int2 m1 = g_motion[((b * NPAIR + f) * NBR + (R1 >> 3)) * NBC + (C >> 3)];
    float p0 = ref[(size_t)(R0 + m0.x) * WW + (C + m0.y)];
    float p1 = ref[(size_t)(R1 + m1.x) * WW + (C + m1.y)];

    out[o0] = t0;
    out[o1] = t1;
    out[TOT + o0] = p0;
    out[TOT + o1] = p1;
}

extern "C" void kernel_launch(void* const* d_in, const int* in_sizes, int n_in,
                              void* d_out, int out_size) {
    const float* x = (const float*)d_in[0];
    float* out = (float*)d_out;

    dim3 gm(8, 64, NBATCH * NPAIR);   // 8 col-tiles x 64 block-rows x (4*14)
    motion_kernel<<<gm, 128>>>(x);

    dim3 go((OUTD + 255) / 256, OUTD / 2, NBATCH * NPAIR);
    out_kernel<<<go, 256>>>(x, out);
}

// round 6
// speedup vs baseline: 1.5230x; 1.5230x over previous
#include <cuda_runtime.h>
#include <float.h>

// Problem constants
#define HH 512
#define WW 512
#define MBS 8          // macroblock size
#define PR 8           // search range
#define NBR 64
#define NBC 64
#define NPAIR 14       // frame pairs actually used (motion[:-1])
#define NBATCH 4
#define CROPX 17
#define OUTD 478       // 512 - 2*17
#define LARGEC 65537.0f
#define MAX_STEPS 16
#define SW 84          // padded smem window stride (cols)

// Motion vectors scratch: (dy, dx) per block. Static device global (no allocs).
__device__ int2 g_motion[NBATCH * NPAIR * NBR * NBC];

// LDSP points as (dx, dy) matching reference ordering; cost uses (y+dy, x+dx).
__constant__ int c_ldsp_dx[9] = { 0, -1, 1, -2, 0, 2, -1, 1, 0 };
__constant__ int c_ldsp_dy[9] = { -2, -1, -1, 0, 0, 0, 1, 1, 2 };
__constant__ int c_sdsp_dx[5] = { 0, -1, 0, 1, 0 };
__constant__ int c_sdsp_dy[5] = { -1, 0, 0, 0, 1 };

// z in [0, 56): motion CTAs — one CTA = 8 macroblocks, 128 threads = 8 groups
// of 16 lanes (lanes 0-8 LDSP candidates, 9-13 speculative SDSP at the center).
// z in [56, 112): target-copy CTAs — pure crop-copy of frame f+2, independent
// of motion; runs concurrently in motion's DRAM shadow (motion is crossbar/
// compute bound with ~0% DRAM).
// SAD accumulation replicates XLA GPU's row-reduction association:
//   pacc[t] = |d|[t] + |d|[t+32], then tree offsets 16,8,4,2,1 (bit-exact argmin).
// Block operand read from smem via float2: all 16 lanes of a group read the
// SAME address -> broadcast, conflict-free (confirmed faster than registers).
__global__ __launch_bounds__(128) void motion_kernel(const float* __restrict__ x,
                                                     float* __restrict__ out) {
    const int zraw = blockIdx.z;

    if (zraw >= NBATCH * NPAIR) {
        // ---- target copy role ----
        const int z = zraw - NBATCH * NPAIR;     // b*NPAIR + f
        const int b = z / NPAIR;
        const int f = z - b * NPAIR;
        const float* tgt = x + ((size_t)(b * 16 + f + 2)) * HH * WW;
        float* o = out + (size_t)z * OUTD * OUTD;
        const int FR = OUTD * OUTD;              // 228484
        int t = (blockIdx.y * 8 + blockIdx.x) * 128 + threadIdx.x;
        const int stride = 8 * 64 * 128;         // 65536
        for (; t < FR; t += stride) {
            int r = t / OUTD;
            int c = t - r * OUTD;
            o[t] = tgt[(size_t)(CROPX + r) * WW + (CROPX + c)];
        }
        return;
    }

    __shared__ float swin[24 * SW];   // reference window rows [i-8, i+16), cols [j0-8, j0+72)
    __shared__ float sblk[8 * 64];    // current-frame blocks for this tile

    const int jt  = blockIdx.x;              // col tile 0..7
    const int bi  = blockIdx.y;              // block row 0..63
    const int bp_ = zraw;                    // b*NPAIR + p, 0..55
    const int b   = bp_ / NPAIR;
    const int p   = bp_ % NPAIR;

    const float* imgI = x + (size_t)(b * 16 + p) * HH * WW;       // reference (t-1)
    const float* imgP = imgI + (size_t)HH * WW;                   // current  (t)

    const int i  = bi * MBS;
    const int j0 = jt * 64;
    const int tid = threadIdx.x;

    // Cooperative loads (clamped; out-of-range rows/cols only back invalid candidates)
    for (int t = tid; t < 24 * 80; t += 128) {
        int r = t / 80, c = t - (t / 80) * 80;
        int gr = i - 8 + r;  gr = gr < 0 ? 0 : (gr > HH - 1 ? HH - 1 : gr);
        int gc = j0 - 8 + c; gc = gc < 0 ? 0 : (gc > WW - 1 ? WW - 1 : gc);
        swin[r * SW + c] = imgI[gr * WW + gc];
    }
    for (int t = tid; t < 8 * 64; t += 128) {
        int r = t >> 6, c = t & 63;
        sblk[t] = imgP[(i + r) * WW + (j0 + c)];
    }
    __syncthreads();

    const int g  = tid >> 4;       // group (macroblock) 0..7
    const int lg = tid & 15;       // lane in group
    const unsigned gmask = 0xFFFFu << (tid & 16);
    const int j = j0 + g * 8;
    const float* bb = sblk + g * 8;

    // SAD mean, XLA association. Block operand from smem via aligned float2
    // (broadcast across the 16-lane group: conflict-free, regs stay ~64).
    auto evalc = [&](int cy, int cx) -> float {
        const float* wp = &swin[(cy - i + 8) * SW + (cx - j0 + 8)];
        float pacc[32];
#pragma unroll
        for (int tp = 0; tp < 16; tp++) {
            int t  = tp * 2;
            int r0 = t >> 3, c0_ = t & 7;   // element t   (pairs never cross rows)
            int r1 = r0 + 4;                // element t+32
            float2 b0 = *(const float2*)(bb + r0 * 64 + c0_);
            float2 b1 = *(const float2*)(bb + r1 * 64 + c0_);
            float w00 = wp[r0 * SW + c0_], w01 = wp[r0 * SW + c0_ + 1];
            float w10 = wp[r1 * SW + c0_], w11 = wp[r1 * SW + c0_ + 1];
            pacc[t]     = fabsf(b0.x - w00) + fabsf(b1.x - w10);
            pacc[t + 1] = fabsf(b0.y - w01) + fabsf(b1.y - w11);
        }
#pragma unroll
        for (int off = 16; off >= 1; off >>= 1)
#pragma unroll
            for (int t = 0; t < 16; t++)
                if (t < off) pacc[t] = pacc[t] + pacc[t + off];
        return pacc[0] * 0.015625f;
    };

    auto costat = [&](int cy, int cx) -> float {
        bool valid = (cy >= 0) && (cy + MBS <= HH) && (cx >= 0) && (cx + MBS <= WW)
                   && (cy - i <= PR) && (i - cy <= PR) && (cx - j <= PR) && (j - cx <= PR);
        float cst = LARGEC;
        if (valid) cst = evalc(cy, cx);
        return cst;
    };

    // Lane role: 0-8 LDSP, 9-13 SDSP(lg-9), 14-15 dup SDSP center (unused).
    const bool isldsp = (lg < 9);
    const int  sdi    = (lg >= 9 && lg < 14) ? (lg - 9) : 2;
    const int  mdy    = isldsp ? c_ldsp_dy[lg] : c_sdsp_dy[sdi];
    const int  mdx    = isldsp ? c_ldsp_dx[lg] : c_sdsp_dx[sdi];

    int y = i, xx = j;
    float my_sdsp = FLT_MAX;
    bool have_sdsp = false;

    for (int k = 0; k < MAX_STEPS; k++) {
        float cost = costat(y + mdy, xx + mdx);
        if (lg >= 9) my_sdsp = cost;

        if (k == 0) {
            // Reference's standalone c0 check == this iteration's lane 4 cost.
            float ctr = __shfl_sync(gmask, cost, 4, 16);
            if (ctr == 0.0f) { have_sdsp = true; break; }
        }

        // LDSP argmin: lexicographic (cost, idx) == jnp.argmin first-index
        float cc = isldsp ? cost : FLT_MAX;
        int  idx = isldsp ? lg : 15;
#pragma unroll
        for (int off = 8; off >= 1; off >>= 1) {
            float oc = __shfl_xor_sync(gmask, cc, off, 16);
            int   oi = __shfl_xor_sync(gmask, idx, off, 16);
            if (oc < cc || (oc == cc && oi < idx)) { cc = oc; idx = oi; }
        }
        if (idx == 4) { have_sdsp = true; break; }   // center: speculative SDSP valid
        y  += c_ldsp_dy[idx];
        xx += c_ldsp_dx[idx];
    }

    // SDSP refinement: use speculative costs, or (rare: MAX_STEPS exit) recompute.
    {
        float sv = FLT_MAX;
        int   si = 15;
        if (have_sdsp) {
            if (lg >= 9 && lg < 14) { sv = my_sdsp; si = lg - 9; }
        } else {
            if (lg < 5) { sv = costat(y + c_sdsp_dy[lg], xx + c_sdsp_dx[lg]); si = lg; }
        }
#pragma unroll
        for (int off = 8; off >= 1; off >>= 1) {
            float oc = __shfl_xor_sync(gmask, sv, off, 16);
            int   oi = __shfl_xor_sync(gmask, si, off, 16);
            if (oc < sv || (oc == sv && oi < si)) { sv = oc; si = oi; }
        }
        y  += c_sdsp_dy[si];
        xx += c_sdsp_dx[si];
    }

    if (lg == 0) {
        g_motion[(bp_ * NBR + bi) * NBC + (jt * 8 + g)] = make_int2(y - i, xx - j);
    }
}

// Pred half only: motion-compensated warp of frame f+1, cropped.
// 2 rows per thread -> 4+ independent loads in flight (L2-latency bound).
__global__ void pred_kernel(const float* __restrict__ x, float* __restrict__ out) {
    int c = blockIdx.x * blockDim.x + threadIdx.x;
    if (c >= OUTD) return;
    int r0 = blockIdx.y * 2;          // rows r0, r0+1 (OUTD=478 even)
    int z  = blockIdx.z;              // b*NPAIR + f
    int b = z / NPAIR;
    int f = z - b * NPAIR;

    const float* ref = x + (size_t)(b * 16 + f + 1) * HH * WW;
    const size_t TOT = (size_t)NBATCH * NPAIR * OUTD * OUTD;

    int C = CROPX + c;
    int R0 = CROPX + r0, R1 = R0 + 1;
    size_t o0 = ((size_t)z * OUTD + r0) * OUTD + c;
    size_t o1 = o0 + OUTD;

    int2 m0 = g_motion[((b * NPAIR + f) * NBR + (R0 >> 3)) * NBC + (C >> 3)];
    int2 m1 = g_motion[((b * NPAIR + f) * NBR + (R1 >> 3)) * NBC + (C >> 3)];
    float p0 = ref[(size_t)(R0 + m0.x) * WW + (C + m0.y)];
    float p1 = ref[(size_t)(R1 + m1.x) * WW + (C + m1.y)];

    out[TOT + o0] = p0;
    out[TOT + o1] = p1;
}

extern "C" void kernel_launch(void* const* d_in, const int* in_sizes, int n_in,
                              void* d_out, int out_size) {
    const float* x = (const float*)d_in[0];
    float* out = (float*)d_out;

    // z: [0,56) motion, [56,112) target crop-copy (independent, overlapped)
    dim3 gm(8, 64, 2 * NBATCH * NPAIR);
    motion_kernel<<<gm, 128>>>(x, out);

    dim3 gp((OUTD + 255) / 256, OUTD / 2, NBATCH * NPAIR);
    pred_kernel<<<gp, 256>>>(x, out);
}

// round 7
// speedup vs baseline: 1.6493x; 1.0829x over previous
#include <cuda_runtime.h>
#include <float.h>

// Problem constants
#define HH 512
#define WW 512
#define MBS 8          // macroblock size
#define PR 8           // search range
#define NBR 64
#define NBC 64
#define NPAIR 14       // frame pairs actually used (motion[:-1])
#define NBATCH 4
#define CROPX 17
#define OUTD 478       // 512 - 2*17
#define LARGEC 65537.0f
#define MAX_STEPS 16
#define SW 84          // padded smem window stride (cols)

// Motion vectors scratch: (dy, dx) per block. Static device global (no allocs).
__device__ int2 g_motion[NBATCH * NPAIR * NBR * NBC];

// LDSP points as (dx, dy) matching reference ordering; cost uses (y+dy, x+dx).
__constant__ int c_ldsp_dx[9] = { 0, -1, 1, -2, 0, 2, -1, 1, 0 };
__constant__ int c_ldsp_dy[9] = { -2, -1, -1, 0, 0, 0, 1, 1, 2 };
__constant__ int c_sdsp_dx[5] = { 0, -1, 0, 1, 0 };
__constant__ int c_sdsp_dy[5] = { -1, 0, 0, 0, 1 };

// One CTA: 8 macroblocks of one block-row segment. 128 threads = 8 groups of 16.
// Per group: lanes 0-8 evaluate the 9 LDSP candidates; lanes 9-13 speculatively
// evaluate the 5 SDSP candidates at the SAME center. When the loop exits with
// pt==4 the speculative SDSP costs equal the reference's final SDSP round.
// SAD accumulation replicates XLA GPU's row-reduction association:
//   pacc[t] = |d|[t] + |d|[t+32], then tree offsets 16,8,4,2,1 (bit-exact argmin).
// Block operand read from smem via float2: all 16 lanes of a group read the
// SAME address -> broadcast, conflict-free (confirmed faster than registers).
__global__ __launch_bounds__(128) void motion_kernel(const float* __restrict__ x) {
    __shared__ float swin[24 * SW];   // reference window rows [i-8, i+16), cols [j0-8, j0+72)
    __shared__ float sblk[8 * 64];    // current-frame blocks for this tile

    const int jt  = blockIdx.x;              // col tile 0..7
    const int bi  = blockIdx.y;              // block row 0..63
    const int bp_ = blockIdx.z;              // b*NPAIR + p, 0..55
    const int b   = bp_ / NPAIR;
    const int p   = bp_ % NPAIR;

    const float* imgI = x + (size_t)(b * 16 + p) * HH * WW;       // reference (t-1)
    const float* imgP = imgI + (size_t)HH * WW;                   // current  (t)

    const int i  = bi * MBS;
    const int j0 = jt * 64;
    const int tid = threadIdx.x;

    // Cooperative loads (clamped; out-of-range rows/cols only back invalid candidates)
    for (int t = tid; t < 24 * 80; t += 128) {
        int r = t / 80, c = t - (t / 80) * 80;
        int gr = i - 8 + r;  gr = gr < 0 ? 0 : (gr > HH - 1 ? HH - 1 : gr);
        int gc = j0 - 8 + c; gc = gc < 0 ? 0 : (gc > WW - 1 ? WW - 1 : gc);
        swin[r * SW + c] = imgI[gr * WW + gc];
    }
    for (int t = tid; t < 8 * 64; t += 128) {
        int r = t >> 6, c = t & 63;
        sblk[t] = imgP[(i + r) * WW + (j0 + c)];
    }
    __syncthreads();

    const int g  = tid >> 4;       // group (macroblock) 0..7
    const int lg = tid & 15;       // lane in group
    const unsigned gmask = 0xFFFFu << (tid & 16);
    const int j = j0 + g * 8;
    const float* bb = sblk + g * 8;

    // SAD mean, XLA association. Block operand from smem via aligned float2
    // (broadcast across the 16-lane group: conflict-free, regs stay ~64).
    auto evalc = [&](int cy, int cx) -> float {
        const float* wp = &swin[(cy - i + 8) * SW + (cx - j0 + 8)];
        float pacc[32];
#pragma unroll
        for (int tp = 0; tp < 16; tp++) {
            int t  = tp * 2;
            int r0 = t >> 3, c0_ = t & 7;   // element t   (pairs never cross rows)
            int r1 = r0 + 4;                // element t+32
            float2 b0 = *(const float2*)(bb + r0 * 64 + c0_);
            float2 b1 = *(const float2*)(bb + r1 * 64 + c0_);
            float w00 = wp[r0 * SW + c0_], w01 = wp[r0 * SW + c0_ + 1];
            float w10 = wp[r1 * SW + c0_], w11 = wp[r1 * SW + c0_ + 1];
            pacc[t]     = fabsf(b0.x - w00) + fabsf(b1.x - w10);
            pacc[t + 1] = fabsf(b0.y - w01) + fabsf(b1.y - w11);
        }
#pragma unroll
        for (int off = 16; off >= 1; off >>= 1)
#pragma unroll
            for (int t = 0; t < 16; t++)
                if (t < off) pacc[t] = pacc[t] + pacc[t + off];
        return pacc[0] * 0.015625f;
    };

    auto costat = [&](int cy, int cx) -> float {
        bool valid = (cy >= 0) && (cy + MBS <= HH) && (cx >= 0) && (cx + MBS <= WW)
                   && (cy - i <= PR) && (i - cy <= PR) && (cx - j <= PR) && (j - cx <= PR);
        float cst = LARGEC;
        if (valid) cst = evalc(cy, cx);
        return cst;
    };

    // Lane role: 0-8 LDSP, 9-13 SDSP(lg-9), 14-15 dup SDSP center (unused).
    const bool isldsp = (lg < 9);
    const int  sdi    = (lg >= 9 && lg < 14) ? (lg - 9) : 2;
    const int  mdy    = isldsp ? c_ldsp_dy[lg] : c_sdsp_dy[sdi];
    const int  mdx    = isldsp ? c_ldsp_dx[lg] : c_sdsp_dx[sdi];

    int y = i, xx = j;
    float my_sdsp = FLT_MAX;
    bool have_sdsp = false;

    for (int k = 0; k < MAX_STEPS; k++) {
        float cost = costat(y + mdy, xx + mdx);
        if (lg >= 9) my_sdsp = cost;

        if (k == 0) {
            // Reference's standalone c0 check == this iteration's lane 4 cost.
            float ctr = __shfl_sync(gmask, cost, 4, 16);
            if (ctr == 0.0f) { have_sdsp = true; break; }
        }

        // LDSP argmin: lexicographic (cost, idx) == jnp.argmin first-index
        float cc = isldsp ? cost : FLT_MAX;
        int  idx = isldsp ? lg : 15;
#pragma unroll
        for (int off = 8; off >= 1; off >>= 1) {
            float oc = __shfl_xor_sync(gmask, cc, off, 16);
            int   oi = __shfl_xor_sync(gmask, idx, off, 16);
            if (oc < cc || (oc == cc && oi < idx)) { cc = oc; idx = oi; }
        }
        if (idx == 4) { have_sdsp = true; break; }   // center: speculative SDSP valid
        y  += c_ldsp_dy[idx];
        xx += c_ldsp_dx[idx];
    }

    // SDSP refinement: use speculative costs, or (rare: MAX_STEPS exit) recompute.
    {
        float sv = FLT_MAX;
        int   si = 15;
        if (have_sdsp) {
            if (lg >= 9 && lg < 14) { sv = my_sdsp; si = lg - 9; }
        } else {
            if (lg < 5) { sv = costat(y + c_sdsp_dy[lg], xx + c_sdsp_dx[lg]); si = lg; }
        }
#pragma unroll
        for (int off = 8; off >= 1; off >>= 1) {
            float oc = __shfl_xor_sync(gmask, sv, off, 16);
            int   oi = __shfl_xor_sync(gmask, si, off, 16);
            if (oc < sv || (oc == sv && oi < si)) { sv = oc; si = oi; }
        }
        y  += c_sdsp_dy[si];
        xx += c_sdsp_dx[si];
    }

    if (lg == 0) {
        g_motion[(bp_ * NBR + bi) * NBC + (jt * 8 + g)] = make_int2(y - i, xx - j);
    }
}

// Output: first half = target (crop of frame f+2), second half = pred
// (motion-compensated warp of frame f+1 through g_motion, cropped).
// 4 rows per thread -> 8+ independent loads in flight (L2-latency bound).
__global__ void out_kernel(const float* __restrict__ x, float* __restrict__ out) {
    int c = blockIdx.x * blockDim.x + threadIdx.x;
    if (c >= OUTD) return;
    int rb = blockIdx.y * 4;          // rows rb .. rb+3 (guarded; 478 = 4*119+2)
    int z  = blockIdx.z;              // b*NPAIR + f
    int b = z / NPAIR;
    int f = z - b * NPAIR;

    const float* base = x + (size_t)b * 16 * HH * WW;
    const float* tgt  = base + (size_t)(f + 2) * HH * WW;
    const float* ref  = base + (size_t)(f + 1) * HH * WW;
    const size_t TOT = (size_t)NBATCH * NPAIR * OUTD * OUTD;
    const int2* mrow = &g_motion[(b * NPAIR + f) * NBR * NBC];

    int C = CROPX + c;
    int cb = C >> 3;

    float t_[4], p_[4];
    int nr = (OUTD - rb) < 4 ? (OUTD - rb) : 4;

#pragma unroll
    for (int u = 0; u < 4; u++) {
        if (u < nr) {
            int R = CROPX + rb + u;
            t_[u] = tgt[(size_t)R * WW + C];
            int2 m = mrow[(R >> 3) * NBC + cb];
            p_[u] = ref[(size_t)(R + m.x) * WW + (C + m.y)];
        }
    }

    size_t o = ((size_t)z * OUTD + rb) * OUTD + c;
#pragma unroll
    for (int u = 0; u < 4; u++) {
        if (u < nr) {
            out[o + (size_t)u * OUTD] = t_[u];
            out[TOT + o + (size_t)u * OUTD] = p_[u];
        }
    }
}

extern "C" void kernel_launch(void* const* d_in, const int* in_sizes, int n_in,
                              void* d_out, int out_size) {
    const float* x = (const float*)d_in[0];
    float* out = (float*)d_out;

    dim3 gm(8, 64, NBATCH * NPAIR);   // 8 col-tiles x 64 block-rows x (4*14)
    motion_kernel<<<gm, 128>>>(x);

    dim3 go((OUTD + 255) / 256, (OUTD + 3) / 4, NBATCH * NPAIR);
    out_kernel<<<go, 256>>>(x, out);
}